// round 1
// baseline (speedup 1.0000x reference)
#include <cuda_runtime.h>
#include <cuda_bf16.h>
#include <cstdint>

// ---------------------------------------------------------------------------
// ACCGraphSAGE: h0 = relu(feat@W0); 3x { agg = mean_in(h); h = relu(agg@Ws[l]) }
// out = concat([h0,h1,h2,h3], dim=1)  -> [N, 512] fp32
// ---------------------------------------------------------------------------

#define MAX_N 50000
#define MAX_E 800000
#define HID 128

// scratch (static device globals: allocation-free rule)
__device__ __align__(16) float g_h[MAX_N * HID];
__device__ __align__(16) float g_agg[MAX_N * HID];
__device__ int g_counts[MAX_N];      // histogram, then reused as scatter cursor
__device__ int g_rowstart[MAX_N + 1];
__device__ int g_csr_src[MAX_E];

// ---------------------------------------------------------------------------
// CSR build
// ---------------------------------------------------------------------------
__global__ void zero_counts_kernel(int* __restrict__ counts, int N) {
    int i = blockIdx.x * blockDim.x + threadIdx.x;
    if (i < N) counts[i] = 0;
}

__global__ void count_kernel(const int* __restrict__ dst, int* __restrict__ counts, int E) {
    int i = blockIdx.x * blockDim.x + threadIdx.x;
    if (i < E) atomicAdd(&counts[dst[i]], 1);
}

// single-block exclusive scan over counts -> rowstart; counts becomes cursor copy
__global__ void scan_kernel(int* __restrict__ counts, int* __restrict__ rowstart, int N) {
    __shared__ int part[1024];
    int tid = threadIdx.x;
    int chunk = (N + 1023) >> 10;
    int s = tid * chunk;
    int e = s + chunk; if (e > N) e = N; if (s > N) s = N;
    int sum = 0;
    for (int i = s; i < e; i++) sum += counts[i];
    part[tid] = sum;
    __syncthreads();
    // Hillis-Steele inclusive scan
    for (int off = 1; off < 1024; off <<= 1) {
        int v = (tid >= off) ? part[tid - off] : 0;
        __syncthreads();
        part[tid] += v;
        __syncthreads();
    }
    int run = (tid == 0) ? 0 : part[tid - 1];
    for (int i = s; i < e; i++) {
        int c = counts[i];
        rowstart[i] = run;
        counts[i] = run;   // cursor for scatter
        run += c;
    }
    if (tid == 1023) rowstart[N] = run;   // == E
}

__global__ void scatter_kernel(const int* __restrict__ src, const int* __restrict__ dst,
                               int* __restrict__ cursor, int* __restrict__ csr, int E) {
    int i = blockIdx.x * blockDim.x + threadIdx.x;
    if (i < E) {
        int pos = atomicAdd(&cursor[dst[i]], 1);
        csr[pos] = src[i];
    }
}

// ---------------------------------------------------------------------------
// Mean aggregation: one warp per dst node, atomic-free, float4 gathers from L2
// ---------------------------------------------------------------------------
__global__ void agg_kernel(const float4* __restrict__ h4,
                           const int* __restrict__ rowstart,
                           const int* __restrict__ csr,
                           float4* __restrict__ agg4, int N) {
    int warp = (blockIdx.x * blockDim.x + threadIdx.x) >> 5;
    int lane = threadIdx.x & 31;
    if (warp >= N) return;
    int s = rowstart[warp];
    int e = rowstart[warp + 1];
    float4 acc = make_float4(0.f, 0.f, 0.f, 0.f);
    int i = s;
    // 4-edge unroll for MLP against L2 latency
    for (; i + 4 <= e; i += 4) {
        int s0 = csr[i], s1 = csr[i + 1], s2 = csr[i + 2], s3 = csr[i + 3];
        float4 v0 = h4[(size_t)s0 * 32 + lane];
        float4 v1 = h4[(size_t)s1 * 32 + lane];
        float4 v2 = h4[(size_t)s2 * 32 + lane];
        float4 v3 = h4[(size_t)s3 * 32 + lane];
        acc.x += v0.x + v1.x + v2.x + v3.x;
        acc.y += v0.y + v1.y + v2.y + v3.y;
        acc.z += v0.z + v1.z + v2.z + v3.z;
        acc.w += v0.w + v1.w + v2.w + v3.w;
    }
    for (; i < e; i++) {
        int sv = csr[i];
        float4 v = h4[(size_t)sv * 32 + lane];
        acc.x += v.x; acc.y += v.y; acc.z += v.z; acc.w += v.w;
    }
    float inv = (e > s) ? (1.f / (float)(e - s)) : 0.f;   // deg=0 -> agg=0 (DGL mean)
    acc.x *= inv; acc.y *= inv; acc.z *= inv; acc.w *= inv;
    agg4[(size_t)warp * 32 + lane] = acc;
}

// ---------------------------------------------------------------------------
// fp32 GEMM + ReLU: Y = relu(X[N,128] @ W[128,128]); writes Hout and Out slice
// block: 256 threads, tile 128 rows; per-thread 8 rows x 8 cols register block
// ---------------------------------------------------------------------------
#define GTPB 256
#define TILE_ROWS 128
#define XPITCH 130   // pad: 8*130 mod 32 = 16 -> row pairs land in distinct banks

__global__ void gemm_relu_kernel(const float* __restrict__ X,
                                 const float* __restrict__ W,
                                 float* __restrict__ Hout,
                                 float* __restrict__ Out,
                                 int N, int outStride, int colOff) {
    extern __shared__ float sm[];
    float* Wsm = sm;                       // 128*128
    float* Xsm = sm + HID * HID;           // TILE_ROWS * XPITCH
    int tid = threadIdx.x;
    int row0 = blockIdx.x * TILE_ROWS;

    for (int i = tid; i < HID * HID; i += GTPB) Wsm[i] = W[i];
    for (int i = tid; i < TILE_ROWS * HID; i += GTPB) {
        int r = i >> 7, c = i & 127;
        int gr = row0 + r;
        Xsm[r * XPITCH + c] = (gr < N) ? X[(size_t)gr * HID + c] : 0.f;
    }
    __syncthreads();

    int cg = tid & 15;    // cols cg + 16*c
    int rg = tid >> 4;    // rows rg*8 + r

    float acc[8][8];
    #pragma unroll
    for (int r = 0; r < 8; r++)
        #pragma unroll
        for (int c = 0; c < 8; c++) acc[r][c] = 0.f;

    #pragma unroll 4
    for (int k = 0; k < HID; k++) {
        float wv[8], xv[8];
        #pragma unroll
        for (int c = 0; c < 8; c++) wv[c] = Wsm[k * HID + cg + 16 * c];
        #pragma unroll
        for (int r = 0; r < 8; r++) xv[r] = Xsm[(rg * 8 + r) * XPITCH + k];
        #pragma unroll
        for (int r = 0; r < 8; r++)
            #pragma unroll
            for (int c = 0; c < 8; c++)
                acc[r][c] = fmaf(xv[r], wv[c], acc[r][c]);
    }

    #pragma unroll
    for (int r = 0; r < 8; r++) {
        int grow = row0 + rg * 8 + r;
        if (grow < N) {
            #pragma unroll
            for (int c = 0; c < 8; c++) {
                float v = acc[r][c];
                v = v > 0.f ? v : 0.f;
                int col = cg + 16 * c;
                Hout[(size_t)grow * HID + col] = v;
                Out[(size_t)grow * outStride + colOff + col] = v;
            }
        }
    }
}

// ---------------------------------------------------------------------------
// launch
// ---------------------------------------------------------------------------
extern "C" void kernel_launch(void* const* d_in, const int* in_sizes, int n_in,
                              void* d_out, int out_size) {
    const float* feat = (const float*)d_in[0];
    const int*   src  = (const int*)d_in[1];
    const int*   dst  = (const int*)d_in[2];
    const float* W0   = (const float*)d_in[3];
    const float* Ws   = (const float*)d_in[4];
    float* out = (float*)d_out;

    int N = in_sizes[0] / HID;
    int E = in_sizes[1];
    int L = in_sizes[4] / (HID * HID);
    int outStride = (L + 1) * HID;

    float* h;       cudaGetSymbolAddress((void**)&h, g_h);
    float* agg;     cudaGetSymbolAddress((void**)&agg, g_agg);
    int* counts;    cudaGetSymbolAddress((void**)&counts, g_counts);
    int* rowstart;  cudaGetSymbolAddress((void**)&rowstart, g_rowstart);
    int* csr;       cudaGetSymbolAddress((void**)&csr, g_csr_src);

    size_t smem = (size_t)(HID * HID + TILE_ROWS * XPITCH) * sizeof(float); // 132096 B
    cudaFuncSetAttribute(gemm_relu_kernel, cudaFuncAttributeMaxDynamicSharedMemorySize,
                         (int)smem);

    // CSR build (counting sort by dst)
    zero_counts_kernel<<<(N + 255) / 256, 256>>>(counts, N);
    count_kernel<<<(E + 255) / 256, 256>>>(dst, counts, E);
    scan_kernel<<<1, 1024>>>(counts, rowstart, N);
    scatter_kernel<<<(E + 255) / 256, 256>>>(src, dst, counts, csr, E);

    int gemm_grid = (N + TILE_ROWS - 1) / TILE_ROWS;
    // h0 = relu(feat @ W0), out[:, 0:128]
    gemm_relu_kernel<<<gemm_grid, GTPB, smem>>>(feat, W0, h, out, N, outStride, 0);

    int agg_grid = (N + 7) / 8;   // 8 warps (nodes) per 256-thread block
    for (int l = 0; l < L; l++) {
        agg_kernel<<<agg_grid, 256>>>((const float4*)h, rowstart, csr, (float4*)agg, N);
        gemm_relu_kernel<<<gemm_grid, GTPB, smem>>>(agg, Ws + (size_t)l * HID * HID,
                                                    h, out, N, outStride, (l + 1) * HID);
    }
    (void)n_in; (void)out_size;
}

// round 2
// speedup vs baseline: 1.0866x; 1.0866x over previous
#include <cuda_runtime.h>
#include <cuda_bf16.h>
#include <cstdint>

// ---------------------------------------------------------------------------
// ACCGraphSAGE: h0 = relu(feat@W0); 3x { agg = mean_in(h); h = relu(agg@Ws[l]) }
// out = concat([h0,h1,h2,h3], dim=1) -> [N, 512] fp32
// R2: GEMM inner loop rewritten around packed fma.rn.f32x2 (SASS FFMA2),
//     X tile stored k-major-transposed so row pairs load as LDS.64 = f32x2.
// ---------------------------------------------------------------------------

#define MAX_N 50000
#define MAX_E 800000
#define HID 128

__device__ __align__(16) float g_h[MAX_N * HID];
__device__ __align__(16) float g_agg[MAX_N * HID];
__device__ int g_counts[MAX_N];
__device__ int g_rowstart[MAX_N + 1];
__device__ int g_csr_src[MAX_E];

// ---------------------------------------------------------------------------
// packed f32x2 helpers
// ---------------------------------------------------------------------------
__device__ __forceinline__ unsigned long long pack_dup(float w) {
    unsigned long long r;
    asm("mov.b64 %0, {%1, %1};" : "=l"(r) : "f"(w));
    return r;
}
__device__ __forceinline__ void ffma2(unsigned long long& d,
                                      unsigned long long a,
                                      unsigned long long b) {
    asm("fma.rn.f32x2 %0, %1, %2, %0;" : "+l"(d) : "l"(a), "l"(b));
}
__device__ __forceinline__ float2 unpack2(unsigned long long v) {
    float2 f;
    asm("mov.b64 {%0, %1}, %2;" : "=f"(f.x), "=f"(f.y) : "l"(v));
    return f;
}

// ---------------------------------------------------------------------------
// CSR build (counting sort by dst)
// ---------------------------------------------------------------------------
__global__ void zero_counts_kernel(int* __restrict__ counts, int N) {
    int i = blockIdx.x * blockDim.x + threadIdx.x;
    if (i < N) counts[i] = 0;
}

__global__ void count_kernel(const int* __restrict__ dst, int* __restrict__ counts, int E) {
    int i = blockIdx.x * blockDim.x + threadIdx.x;
    if (i < E) atomicAdd(&counts[dst[i]], 1);
}

__global__ void scan_kernel(int* __restrict__ counts, int* __restrict__ rowstart, int N) {
    __shared__ int part[1024];
    int tid = threadIdx.x;
    int chunk = (N + 1023) >> 10;
    int s = tid * chunk;
    int e = s + chunk; if (e > N) e = N; if (s > N) s = N;
    int sum = 0;
    for (int i = s; i < e; i++) sum += counts[i];
    part[tid] = sum;
    __syncthreads();
    for (int off = 1; off < 1024; off <<= 1) {
        int v = (tid >= off) ? part[tid - off] : 0;
        __syncthreads();
        part[tid] += v;
        __syncthreads();
    }
    int run = (tid == 0) ? 0 : part[tid - 1];
    for (int i = s; i < e; i++) {
        int c = counts[i];
        rowstart[i] = run;
        counts[i] = run;
        run += c;
    }
    if (tid == 1023) rowstart[N] = run;
}

__global__ void scatter_kernel(const int* __restrict__ src, const int* __restrict__ dst,
                               int* __restrict__ cursor, int* __restrict__ csr, int E) {
    int i = blockIdx.x * blockDim.x + threadIdx.x;
    if (i < E) {
        int pos = atomicAdd(&cursor[dst[i]], 1);
        csr[pos] = src[i];
    }
}

// ---------------------------------------------------------------------------
// Mean aggregation: one warp per dst node, atomic-free, float4 gathers from L2
// ---------------------------------------------------------------------------
__global__ void agg_kernel(const float4* __restrict__ h4,
                           const int* __restrict__ rowstart,
                           const int* __restrict__ csr,
                           float4* __restrict__ agg4, int N) {
    int warp = (blockIdx.x * blockDim.x + threadIdx.x) >> 5;
    int lane = threadIdx.x & 31;
    if (warp >= N) return;
    int s = rowstart[warp];
    int e = rowstart[warp + 1];
    float4 acc = make_float4(0.f, 0.f, 0.f, 0.f);
    int i = s;
    for (; i + 4 <= e; i += 4) {
        int s0 = csr[i], s1 = csr[i + 1], s2 = csr[i + 2], s3 = csr[i + 3];
        float4 v0 = h4[(size_t)s0 * 32 + lane];
        float4 v1 = h4[(size_t)s1 * 32 + lane];
        float4 v2 = h4[(size_t)s2 * 32 + lane];
        float4 v3 = h4[(size_t)s3 * 32 + lane];
        acc.x += v0.x + v1.x + v2.x + v3.x;
        acc.y += v0.y + v1.y + v2.y + v3.y;
        acc.z += v0.z + v1.z + v2.z + v3.z;
        acc.w += v0.w + v1.w + v2.w + v3.w;
    }
    for (; i < e; i++) {
        int sv = csr[i];
        float4 v = h4[(size_t)sv * 32 + lane];
        acc.x += v.x; acc.y += v.y; acc.z += v.z; acc.w += v.w;
    }
    float inv = (e > s) ? (1.f / (float)(e - s)) : 0.f;
    acc.x *= inv; acc.y *= inv; acc.z *= inv; acc.w *= inv;
    agg4[(size_t)warp * 32 + lane] = acc;
}

// ---------------------------------------------------------------------------
// fp32 GEMM + ReLU via packed FFMA2.
// Block 256 thr, tile 128 rows. lane (0..31) owns 4 contiguous cols [lane*4,+4);
// warp (0..7) owns 16 rows [warp*16,+16) as 8 row-pairs (f32x2).
// XT[k][row] transposed in smem (pitch 130): row-pair = one LDS.64.
// ---------------------------------------------------------------------------
#define GTPB 256
#define TILE_ROWS 128
#define XTP 130   // even (8B-aligned b64 reads); store stride 130 mod 32 = 2-way

__global__ void __launch_bounds__(GTPB, 1)
gemm_relu_kernel(const float* __restrict__ X,
                 const float* __restrict__ W,
                 float* __restrict__ Hout,
                 float* __restrict__ Out,
                 int N, int outStride, int colOff) {
    extern __shared__ float sm[];
    float* Wsm = sm;                 // [128][128] k-major
    float* XT  = sm + HID * HID;     // [128 k][XTP] transposed
    int tid = threadIdx.x;
    int lane = tid & 31;
    int w = tid >> 5;
    int row0 = blockIdx.x * TILE_ROWS;

    for (int i = tid; i < HID * HID; i += GTPB) Wsm[i] = W[i];
    for (int i = tid; i < TILE_ROWS * HID; i += GTPB) {
        int r = i >> 7, c = i & 127;
        int gr = row0 + r;
        XT[c * XTP + r] = (gr < N) ? X[(size_t)gr * HID + c] : 0.f;
    }
    __syncthreads();

    unsigned long long acc[8][4];
    #pragma unroll
    for (int p = 0; p < 8; p++)
        #pragma unroll
        for (int c = 0; c < 4; c++) acc[p][c] = 0ull;

    const int rowbase = w * 16;
    #pragma unroll 2
    for (int k = 0; k < HID; k++) {
        float4 wv = *reinterpret_cast<const float4*>(&Wsm[k * HID + lane * 4]);
        unsigned long long wd0 = pack_dup(wv.x);
        unsigned long long wd1 = pack_dup(wv.y);
        unsigned long long wd2 = pack_dup(wv.z);
        unsigned long long wd3 = pack_dup(wv.w);
        const unsigned long long* xr =
            reinterpret_cast<const unsigned long long*>(&XT[k * XTP + rowbase]);
        #pragma unroll
        for (int p = 0; p < 8; p++) {
            unsigned long long xp = xr[p];   // rows (rowbase+2p, rowbase+2p+1)
            ffma2(acc[p][0], xp, wd0);
            ffma2(acc[p][1], xp, wd1);
            ffma2(acc[p][2], xp, wd2);
            ffma2(acc[p][3], xp, wd3);
        }
    }

    #pragma unroll
    for (int p = 0; p < 8; p++) {
        float2 c0 = unpack2(acc[p][0]);
        float2 c1 = unpack2(acc[p][1]);
        float2 c2 = unpack2(acc[p][2]);
        float2 c3 = unpack2(acc[p][3]);
        int r0 = row0 + rowbase + 2 * p;
        if (r0 < N) {
            float4 v = make_float4(fmaxf(c0.x, 0.f), fmaxf(c1.x, 0.f),
                                   fmaxf(c2.x, 0.f), fmaxf(c3.x, 0.f));
            *reinterpret_cast<float4*>(&Hout[(size_t)r0 * HID + lane * 4]) = v;
            *reinterpret_cast<float4*>(&Out[(size_t)r0 * outStride + colOff + lane * 4]) = v;
        }
        if (r0 + 1 < N) {
            float4 v = make_float4(fmaxf(c0.y, 0.f), fmaxf(c1.y, 0.f),
                                   fmaxf(c2.y, 0.f), fmaxf(c3.y, 0.f));
            *reinterpret_cast<float4*>(&Hout[(size_t)(r0 + 1) * HID + lane * 4]) = v;
            *reinterpret_cast<float4*>(&Out[(size_t)(r0 + 1) * outStride + colOff + lane * 4]) = v;
        }
    }
}

// ---------------------------------------------------------------------------
// launch
// ---------------------------------------------------------------------------
extern "C" void kernel_launch(void* const* d_in, const int* in_sizes, int n_in,
                              void* d_out, int out_size) {
    const float* feat = (const float*)d_in[0];
    const int*   src  = (const int*)d_in[1];
    const int*   dst  = (const int*)d_in[2];
    const float* W0   = (const float*)d_in[3];
    const float* Ws   = (const float*)d_in[4];
    float* out = (float*)d_out;

    int N = in_sizes[0] / HID;
    int E = in_sizes[1];
    int L = in_sizes[4] / (HID * HID);
    int outStride = (L + 1) * HID;

    float* h;       cudaGetSymbolAddress((void**)&h, g_h);
    float* agg;     cudaGetSymbolAddress((void**)&agg, g_agg);
    int* counts;    cudaGetSymbolAddress((void**)&counts, g_counts);
    int* rowstart;  cudaGetSymbolAddress((void**)&rowstart, g_rowstart);
    int* csr;       cudaGetSymbolAddress((void**)&csr, g_csr_src);

    size_t smem = (size_t)(HID * HID + HID * XTP) * sizeof(float); // 132096 B
    cudaFuncSetAttribute(gemm_relu_kernel, cudaFuncAttributeMaxDynamicSharedMemorySize,
                         (int)smem);

    zero_counts_kernel<<<(N + 255) / 256, 256>>>(counts, N);
    count_kernel<<<(E + 255) / 256, 256>>>(dst, counts, E);
    scan_kernel<<<1, 1024>>>(counts, rowstart, N);
    scatter_kernel<<<(E + 255) / 256, 256>>>(src, dst, counts, csr, E);

    int gemm_grid = (N + TILE_ROWS - 1) / TILE_ROWS;
    gemm_relu_kernel<<<gemm_grid, GTPB, smem>>>(feat, W0, h, out, N, outStride, 0);

    int agg_grid = (N + 7) / 8;
    for (int l = 0; l < L; l++) {
        agg_kernel<<<agg_grid, 256>>>((const float4*)h, rowstart, csr, (float4*)agg, N);
        gemm_relu_kernel<<<gemm_grid, GTPB, smem>>>(agg, Ws + (size_t)l * HID * HID,
                                                    h, out, N, outStride, (l + 1) * HID);
    }
    (void)n_in; (void)out_size;
}

// round 4
// speedup vs baseline: 1.4022x; 1.2905x over previous
#include <cuda_runtime.h>
#include <cuda_bf16.h>
#include <cstdint>

// ---------------------------------------------------------------------------
// ACCGraphSAGE: h0 = relu(feat@W0); 3x { agg = mean_in(h); h = relu(agg@Ws[l]) }
// out = concat([h0..h3], dim=1) -> [N, 512] fp32
// R4: GEMMs via warp-level mma.sync bf16 (sm_80 PTX tier, works under
//     compute_100) with 2-way hi/lo split -> ~fp24 precision, fp32 accum.
//     h written once directly into out; agg reads strided rows from out.
// ---------------------------------------------------------------------------

#define MAX_N 50000
#define MAX_E 800000
#define HID 128

__device__ __align__(16) float g_agg[MAX_N * HID];
__device__ int g_counts[MAX_N];
__device__ int g_rowstart[MAX_N + 1];
__device__ int g_csr_src[MAX_E];

// ---------------------------------------------------------------------------
// helpers
// ---------------------------------------------------------------------------
__device__ __forceinline__ uint32_t s2u(const void* p) {
    uint32_t a;
    asm("{ .reg .u64 t; cvta.to.shared.u64 t, %1; cvt.u32.u64 %0, t; }"
        : "=r"(a) : "l"(p));
    return a;
}

// swizzled byte offset inside a [128 rows][128 bf16] tile, 256B row pitch.
// 16B chunks XOR'd with (row & 7): conflict-free ldmatrix among any 8
// consecutive rows. kelem need not be 8-aligned for scalar/paired stores.
__device__ __forceinline__ uint32_t swz(uint32_t row, uint32_t kelem) {
    return row * 256u + ((((kelem >> 3) ^ (row & 7u)) & 15u) << 4) +
           ((kelem & 7u) << 1);
}

__device__ __forceinline__ void ldsm_x4(uint32_t* d, uint32_t addr) {
    asm volatile("ldmatrix.sync.aligned.m8n8.x4.shared.b16 {%0,%1,%2,%3}, [%4];"
                 : "=r"(d[0]), "=r"(d[1]), "=r"(d[2]), "=r"(d[3]) : "r"(addr));
}
__device__ __forceinline__ void ldsm_x2t(uint32_t* d, uint32_t addr) {
    asm volatile("ldmatrix.sync.aligned.m8n8.x2.trans.shared.b16 {%0,%1}, [%2];"
                 : "=r"(d[0]), "=r"(d[1]) : "r"(addr));
}
__device__ __forceinline__ void mma_bf16(float* c, const uint32_t* a,
                                         const uint32_t* b) {
    asm volatile(
        "mma.sync.aligned.m16n8k16.row.col.f32.bf16.bf16.f32 "
        "{%0,%1,%2,%3}, {%4,%5,%6,%7}, {%8,%9}, {%0,%1,%2,%3};"
        : "+f"(c[0]), "+f"(c[1]), "+f"(c[2]), "+f"(c[3])
        : "r"(a[0]), "r"(a[1]), "r"(a[2]), "r"(a[3]), "r"(b[0]), "r"(b[1]));
}

// ---------------------------------------------------------------------------
// CSR build (counting sort by dst)
// ---------------------------------------------------------------------------
__global__ void zero_counts_kernel(int* __restrict__ counts, int N) {
    int i = blockIdx.x * blockDim.x + threadIdx.x;
    if (i < N) counts[i] = 0;
}

__global__ void count_kernel(const int* __restrict__ dst, int* __restrict__ counts, int E) {
    int i = blockIdx.x * blockDim.x + threadIdx.x;
    if (i < E) atomicAdd(&counts[dst[i]], 1);
}

__global__ void scan_kernel(int* __restrict__ counts, int* __restrict__ rowstart, int N) {
    __shared__ int part[1024];
    int tid = threadIdx.x;
    int chunk = (N + 1023) >> 10;
    int s = tid * chunk;
    int e = s + chunk; if (e > N) e = N; if (s > N) s = N;
    int sum = 0;
    for (int i = s; i < e; i++) sum += counts[i];
    part[tid] = sum;
    __syncthreads();
    for (int off = 1; off < 1024; off <<= 1) {
        int v = (tid >= off) ? part[tid - off] : 0;
        __syncthreads();
        part[tid] += v;
        __syncthreads();
    }
    int run = (tid == 0) ? 0 : part[tid - 1];
    for (int i = s; i < e; i++) {
        int c = counts[i];
        rowstart[i] = run;
        counts[i] = run;
        run += c;
    }
    if (tid == 1023) rowstart[N] = run;
}

__global__ void scatter_kernel(const int* __restrict__ src, const int* __restrict__ dst,
                               int* __restrict__ cursor, int* __restrict__ csr, int E) {
    int i = blockIdx.x * blockDim.x + threadIdx.x;
    if (i < E) {
        int pos = atomicAdd(&cursor[dst[i]], 1);
        csr[pos] = src[i];
    }
}

// ---------------------------------------------------------------------------
// Mean aggregation: one warp per dst node; gathers strided rows from `out`
// ---------------------------------------------------------------------------
__global__ void agg_kernel(const float4* __restrict__ h4, int rs4,
                           const int* __restrict__ rowstart,
                           const int* __restrict__ csr,
                           float4* __restrict__ agg4, int N) {
    int warp = (blockIdx.x * blockDim.x + threadIdx.x) >> 5;
    int lane = threadIdx.x & 31;
    if (warp >= N) return;
    int s = rowstart[warp];
    int e = rowstart[warp + 1];
    float4 acc = make_float4(0.f, 0.f, 0.f, 0.f);
    int i = s;
    for (; i + 4 <= e; i += 4) {
        int s0 = csr[i], s1 = csr[i + 1], s2 = csr[i + 2], s3 = csr[i + 3];
        float4 v0 = h4[(size_t)s0 * rs4 + lane];
        float4 v1 = h4[(size_t)s1 * rs4 + lane];
        float4 v2 = h4[(size_t)s2 * rs4 + lane];
        float4 v3 = h4[(size_t)s3 * rs4 + lane];
        acc.x += v0.x + v1.x + v2.x + v3.x;
        acc.y += v0.y + v1.y + v2.y + v3.y;
        acc.z += v0.z + v1.z + v2.z + v3.z;
        acc.w += v0.w + v1.w + v2.w + v3.w;
    }
    for (; i < e; i++) {
        int sv = csr[i];
        float4 v = h4[(size_t)sv * rs4 + lane];
        acc.x += v.x; acc.y += v.y; acc.z += v.z; acc.w += v.w;
    }
    float inv = (e > s) ? (1.f / (float)(e - s)) : 0.f;
    acc.x *= inv; acc.y *= inv; acc.z *= inv; acc.w *= inv;
    agg4[(size_t)warp * 32 + lane] = acc;
}

// ---------------------------------------------------------------------------
// mma.sync GEMM + ReLU: Y = relu(X[128-tile,128] @ W[128,128]) -> out block.
// smem tiles (32KB each, swizzled): XH,XL = X hi/lo row-major [r][k];
//                                   BH,BL = W hi/lo row-major [k][n].
// 8 warps; warp w owns rows (w&3)*32..+32, cols (w>>2)*64..+64.
// Passes: XH*BH + XH*BL + XL*BH (fp32 accum in registers).
// ---------------------------------------------------------------------------
#define GT 256
#define T_XH 0
#define T_XL 32768
#define T_BH 65536
#define T_BL 98304
#define GEMM_SMEM 131072

__global__ void __launch_bounds__(GT)
gemm_mma_kernel(const float* __restrict__ X, const float* __restrict__ W,
                float* __restrict__ outBlk, int N, int outStride) {
    extern __shared__ char smem[];
    uint32_t sb = s2u(smem);
    int tid = threadIdx.x;
    int lane = tid & 31;
    int w = tid >> 5;
    int row0 = blockIdx.x * 128;

    // X tile -> XH/XL (row-major, swizzled, coalesced)
    for (int idx = tid; idx < 128 * 32; idx += GT) {
        int r = idx >> 5;
        int k = (idx & 31) * 4;
        float4 v = make_float4(0.f, 0.f, 0.f, 0.f);
        int gr = row0 + r;
        if (gr < N) v = *reinterpret_cast<const float4*>(X + (size_t)gr * HID + k);
        __nv_bfloat162 h01 = __floats2bfloat162_rn(v.x, v.y);
        __nv_bfloat162 h23 = __floats2bfloat162_rn(v.z, v.w);
        __nv_bfloat162 l01 = __floats2bfloat162_rn(v.x - __bfloat162float(h01.x),
                                                   v.y - __bfloat162float(h01.y));
        __nv_bfloat162 l23 = __floats2bfloat162_rn(v.z - __bfloat162float(h23.x),
                                                   v.w - __bfloat162float(h23.y));
        uint32_t o0 = swz(r, k), o1 = swz(r, k + 2);
        *reinterpret_cast<__nv_bfloat162*>(smem + T_XH + o0) = h01;
        *reinterpret_cast<__nv_bfloat162*>(smem + T_XH + o1) = h23;
        *reinterpret_cast<__nv_bfloat162*>(smem + T_XL + o0) = l01;
        *reinterpret_cast<__nv_bfloat162*>(smem + T_XL + o1) = l23;
    }
    // W -> BH/BL (row-major [k][n], swizzled, coalesced; no transpose)
    for (int idx = tid; idx < 128 * 32; idx += GT) {
        int k = idx >> 5;
        int n = (idx & 31) * 4;
        float4 v = *reinterpret_cast<const float4*>(W + (size_t)k * HID + n);
        __nv_bfloat162 h01 = __floats2bfloat162_rn(v.x, v.y);
        __nv_bfloat162 h23 = __floats2bfloat162_rn(v.z, v.w);
        __nv_bfloat162 l01 = __floats2bfloat162_rn(v.x - __bfloat162float(h01.x),
                                                   v.y - __bfloat162float(h01.y));
        __nv_bfloat162 l23 = __floats2bfloat162_rn(v.z - __bfloat162float(h23.x),
                                                   v.w - __bfloat162float(h23.y));
        uint32_t o0 = swz(k, n), o1 = swz(k, n + 2);
        *reinterpret_cast<__nv_bfloat162*>(smem + T_BH + o0) = h01;
        *reinterpret_cast<__nv_bfloat162*>(smem + T_BH + o1) = h23;
        *reinterpret_cast<__nv_bfloat162*>(smem + T_BL + o0) = l01;
        *reinterpret_cast<__nv_bfloat162*>(smem + T_BL + o1) = l23;
    }
    __syncthreads();

    const int rw = (w & 3) * 32;
    const int cw = (w >> 2) * 64;

    float acc[2][8][4];
    #pragma unroll
    for (int i = 0; i < 2; i++)
        #pragma unroll
        for (int j = 0; j < 8; j++)
            #pragma unroll
            for (int q = 0; q < 4; q++) acc[i][j][q] = 0.f;

    const int l2 = lane & 15;
    #pragma unroll
    for (int pass = 0; pass < 3; pass++) {
        const uint32_t aBase = sb + (pass == 2 ? T_XL : T_XH);
        const uint32_t bBase = sb + (pass == 1 ? T_BL : T_BH);
        #pragma unroll
        for (int kc = 0; kc < 8; kc++) {
            uint32_t a[2][4];
            #pragma unroll
            for (int i = 0; i < 2; i++) {
                uint32_t ar = (uint32_t)(rw + i * 16 + (lane & 15));
                uint32_t ak = (uint32_t)(kc * 16 + (lane >> 4) * 8);
                ldsm_x4(a[i], aBase + swz(ar, ak));
            }
            #pragma unroll
            for (int j = 0; j < 8; j++) {
                uint32_t b[2];
                uint32_t bk = (uint32_t)(kc * 16 + (l2 & 7) + ((l2 >> 3) & 1) * 8);
                uint32_t bn = (uint32_t)(cw + j * 8);
                ldsm_x2t(b, bBase + swz(bk, bn));
                mma_bf16(acc[0][j], a[0], b);
                mma_bf16(acc[1][j], a[1], b);
            }
        }
    }

    // epilogue: relu + direct stores (float2 per fragment half)
    #pragma unroll
    for (int i = 0; i < 2; i++) {
        int rA = row0 + rw + i * 16 + (lane >> 2);
        int rB = rA + 8;
        #pragma unroll
        for (int j = 0; j < 8; j++) {
            int c = cw + j * 8 + (lane & 3) * 2;
            if (rA < N) {
                float2 v = make_float2(fmaxf(acc[i][j][0], 0.f),
                                       fmaxf(acc[i][j][1], 0.f));
                *reinterpret_cast<float2*>(outBlk + (size_t)rA * outStride + c) = v;
            }
            if (rB < N) {
                float2 v = make_float2(fmaxf(acc[i][j][2], 0.f),
                                       fmaxf(acc[i][j][3], 0.f));
                *reinterpret_cast<float2*>(outBlk + (size_t)rB * outStride + c) = v;
            }
        }
    }
}

// ---------------------------------------------------------------------------
// launch
// ---------------------------------------------------------------------------
extern "C" void kernel_launch(void* const* d_in, const int* in_sizes, int n_in,
                              void* d_out, int out_size) {
    const float* feat = (const float*)d_in[0];
    const int*   src  = (const int*)d_in[1];
    const int*   dst  = (const int*)d_in[2];
    const float* W0   = (const float*)d_in[3];
    const float* Ws   = (const float*)d_in[4];
    float* out = (float*)d_out;

    int N = in_sizes[0] / HID;
    int E = in_sizes[1];
    int L = in_sizes[4] / (HID * HID);
    int outStride = (L + 1) * HID;

    float* agg;     cudaGetSymbolAddress((void**)&agg, g_agg);
    int* counts;    cudaGetSymbolAddress((void**)&counts, g_counts);
    int* rowstart;  cudaGetSymbolAddress((void**)&rowstart, g_rowstart);
    int* csr;       cudaGetSymbolAddress((void**)&csr, g_csr_src);

    cudaFuncSetAttribute(gemm_mma_kernel, cudaFuncAttributeMaxDynamicSharedMemorySize,
                         GEMM_SMEM);

    // CSR build
    zero_counts_kernel<<<(N + 255) / 256, 256>>>(counts, N);
    count_kernel<<<(E + 255) / 256, 256>>>(dst, counts, E);
    scan_kernel<<<1, 1024>>>(counts, rowstart, N);
    scatter_kernel<<<(E + 255) / 256, 256>>>(src, dst, counts, csr, E);

    int gemm_grid = (N + 127) / 128;
    // layer 0: h0 = relu(feat @ W0) -> out[:, 0:128]
    gemm_mma_kernel<<<gemm_grid, GT, GEMM_SMEM>>>(feat, W0, out, N, outStride);

    int agg_grid = (N + 7) / 8;
    for (int l = 0; l < L; l++) {
        agg_kernel<<<agg_grid, 256>>>(
            reinterpret_cast<const float4*>(out + (size_t)l * HID), outStride / 4,
            rowstart, csr, reinterpret_cast<float4*>(agg), N);
        gemm_mma_kernel<<<gemm_grid, GT, GEMM_SMEM>>>(
            agg, Ws + (size_t)l * HID * HID, out + (size_t)(l + 1) * HID, N, outStride);
    }
    (void)n_in; (void)out_size;
}

// round 5
// speedup vs baseline: 1.7431x; 1.2431x over previous
#include <cuda_runtime.h>
#include <cuda_bf16.h>
#include <cstdint>

// ---------------------------------------------------------------------------
// ACCGraphSAGE: h0 = relu(feat@W0); 3x { agg = mean_in(h); h = relu(agg@Ws[l]) }
// out = concat([h0..h3], dim=1) -> [N, 512] fp32
// R5: all GEMM inputs pre-converted to bf16 hi/lo in pre-swizzled global tile
//     layout (weights once; agg emits hi/lo directly). GEMM = linear-copy
//     prologue + mma.sync, 64-row tiles, 96KB smem, 2 CTAs/SM.
// ---------------------------------------------------------------------------

#define MAX_N 50000
#define MAX_E 800000
#define HID 128
#define NTILES ((MAX_N + 63) / 64)     // 782

__device__ int g_counts[MAX_N];
__device__ int g_rowstart[MAX_N + 1];
__device__ int g_csr_src[MAX_E];
// X hi/lo in swizzled 64x128 tiles (16KB per tile); zero-init padding rows
__device__ __align__(16) unsigned char g_xh[NTILES * 16384];
__device__ __align__(16) unsigned char g_xl[NTILES * 16384];
// W hi/lo, 4 layers x 128x128 swizzled tiles (32KB each)
__device__ __align__(16) unsigned char g_wh[4 * 32768];
__device__ __align__(16) unsigned char g_wl[4 * 32768];

// ---------------------------------------------------------------------------
// helpers
// ---------------------------------------------------------------------------
__device__ __forceinline__ uint32_t s2u(const void* p) {
    uint32_t a;
    asm("{ .reg .u64 t; cvta.to.shared.u64 t, %1; cvt.u32.u64 %0, t; }"
        : "=r"(a) : "l"(p));
    return a;
}

// swizzled byte offset inside a tile of [rows][128 bf16], 256B row pitch.
// 16B chunks XOR'd with (row & 7): conflict-free ldmatrix.
__device__ __forceinline__ uint32_t swz(uint32_t row, uint32_t kelem) {
    return row * 256u + ((((kelem >> 3) ^ (row & 7u)) & 15u) << 4) +
           ((kelem & 7u) << 1);
}

__device__ __forceinline__ void ldsm_x4(uint32_t* d, uint32_t addr) {
    asm volatile("ldmatrix.sync.aligned.m8n8.x4.shared.b16 {%0,%1,%2,%3}, [%4];"
                 : "=r"(d[0]), "=r"(d[1]), "=r"(d[2]), "=r"(d[3]) : "r"(addr));
}
__device__ __forceinline__ void ldsm_x2t(uint32_t* d, uint32_t addr) {
    asm volatile("ldmatrix.sync.aligned.m8n8.x2.trans.shared.b16 {%0,%1}, [%2];"
                 : "=r"(d[0]), "=r"(d[1]) : "r"(addr));
}
__device__ __forceinline__ void mma_bf16(float* c, const uint32_t* a,
                                         const uint32_t* b) {
    asm volatile(
        "mma.sync.aligned.m16n8k16.row.col.f32.bf16.bf16.f32 "
        "{%0,%1,%2,%3}, {%4,%5,%6,%7}, {%8,%9}, {%0,%1,%2,%3};"
        : "+f"(c[0]), "+f"(c[1]), "+f"(c[2]), "+f"(c[3])
        : "r"(a[0]), "r"(a[1]), "r"(a[2]), "r"(a[3]), "r"(b[0]), "r"(b[1]));
}

// write fp32 quad as hi/lo bf16 pairs at swizzled tile offsets
__device__ __forceinline__ void store_hilo(unsigned char* xh, unsigned char* xl,
                                           size_t tileBase, uint32_t r, uint32_t k,
                                           float4 v) {
    __nv_bfloat162 h01 = __floats2bfloat162_rn(v.x, v.y);
    __nv_bfloat162 h23 = __floats2bfloat162_rn(v.z, v.w);
    __nv_bfloat162 l01 = __floats2bfloat162_rn(v.x - __bfloat162float(h01.x),
                                               v.y - __bfloat162float(h01.y));
    __nv_bfloat162 l23 = __floats2bfloat162_rn(v.z - __bfloat162float(h23.x),
                                               v.w - __bfloat162float(h23.y));
    uint32_t o0 = swz(r, k), o1 = swz(r, k + 2);
    *reinterpret_cast<__nv_bfloat162*>(xh + tileBase + o0) = h01;
    *reinterpret_cast<__nv_bfloat162*>(xh + tileBase + o1) = h23;
    *reinterpret_cast<__nv_bfloat162*>(xl + tileBase + o0) = l01;
    *reinterpret_cast<__nv_bfloat162*>(xl + tileBase + o1) = l23;
}

// ---------------------------------------------------------------------------
// CSR build (counting sort by dst)
// ---------------------------------------------------------------------------
__global__ void zero_counts_kernel(int* __restrict__ counts, int N) {
    int i = blockIdx.x * blockDim.x + threadIdx.x;
    if (i < N) counts[i] = 0;
}

__global__ void count_kernel(const int* __restrict__ dst, int* __restrict__ counts, int E) {
    int i = blockIdx.x * blockDim.x + threadIdx.x;
    if (i < E) atomicAdd(&counts[dst[i]], 1);
}

__global__ void scan_kernel(int* __restrict__ counts, int* __restrict__ rowstart, int N) {
    __shared__ int part[1024];
    int tid = threadIdx.x;
    int chunk = (N + 1023) >> 10;
    int s = tid * chunk;
    int e = s + chunk; if (e > N) e = N; if (s > N) s = N;
    int sum = 0;
    for (int i = s; i < e; i++) sum += counts[i];
    part[tid] = sum;
    __syncthreads();
    for (int off = 1; off < 1024; off <<= 1) {
        int v = (tid >= off) ? part[tid - off] : 0;
        __syncthreads();
        part[tid] += v;
        __syncthreads();
    }
    int run = (tid == 0) ? 0 : part[tid - 1];
    for (int i = s; i < e; i++) {
        int c = counts[i];
        rowstart[i] = run;
        counts[i] = run;
        run += c;
    }
    if (tid == 1023) rowstart[N] = run;
}

__global__ void scatter_kernel(const int* __restrict__ src, const int* __restrict__ dst,
                               int* __restrict__ cursor, int* __restrict__ csr, int E) {
    int i = blockIdx.x * blockDim.x + threadIdx.x;
    if (i < E) {
        int pos = atomicAdd(&cursor[dst[i]], 1);
        csr[pos] = src[i];
    }
}

// ---------------------------------------------------------------------------
// converters: fp32 [rows,128] -> swizzled hi/lo bf16 tiles
// ---------------------------------------------------------------------------
__global__ void feat_conv_kernel(const float* __restrict__ X,
                                 unsigned char* __restrict__ xh,
                                 unsigned char* __restrict__ xl, int N) {
    int idx = blockIdx.x * blockDim.x + threadIdx.x;
    if (idx >= N * 32) return;
    int r = idx >> 5;
    int k = (idx & 31) * 4;
    float4 v = *reinterpret_cast<const float4*>(X + (size_t)r * HID + k);
    store_hilo(xh, xl, (size_t)(r >> 6) * 16384, (uint32_t)(r & 63), (uint32_t)k, v);
}

__global__ void w_conv_kernel(const float* __restrict__ W0,
                              const float* __restrict__ Ws,
                              unsigned char* __restrict__ wh,
                              unsigned char* __restrict__ wl, int L) {
    int idx = blockIdx.x * blockDim.x + threadIdx.x;
    if (idx >= (L + 1) * 128 * 32) return;
    int layer = idx >> 12;
    int rem = idx & 4095;
    int k = rem >> 5;
    int n = (rem & 31) * 4;
    const float* w = (layer == 0) ? W0 : (Ws + (size_t)(layer - 1) * HID * HID);
    float4 v = *reinterpret_cast<const float4*>(w + (size_t)k * HID + n);
    store_hilo(wh, wl, (size_t)layer * 32768, (uint32_t)k, (uint32_t)n, v);
}

// ---------------------------------------------------------------------------
// Mean aggregation: one warp per dst node; gathers strided fp32 rows from
// `out`, emits hi/lo bf16 into swizzled tiles.
// ---------------------------------------------------------------------------
__global__ void agg_kernel(const float4* __restrict__ h4, int rs4,
                           const int* __restrict__ rowstart,
                           const int* __restrict__ csr,
                           unsigned char* __restrict__ xh,
                           unsigned char* __restrict__ xl, int N) {
    int node = (blockIdx.x * blockDim.x + threadIdx.x) >> 5;
    int lane = threadIdx.x & 31;
    if (node >= N) return;
    int s = rowstart[node];
    int e = rowstart[node + 1];
    float4 acc = make_float4(0.f, 0.f, 0.f, 0.f);
    int i = s;
    for (; i + 4 <= e; i += 4) {
        int s0 = csr[i], s1 = csr[i + 1], s2 = csr[i + 2], s3 = csr[i + 3];
        float4 v0 = h4[(size_t)s0 * rs4 + lane];
        float4 v1 = h4[(size_t)s1 * rs4 + lane];
        float4 v2 = h4[(size_t)s2 * rs4 + lane];
        float4 v3 = h4[(size_t)s3 * rs4 + lane];
        acc.x += v0.x + v1.x + v2.x + v3.x;
        acc.y += v0.y + v1.y + v2.y + v3.y;
        acc.z += v0.z + v1.z + v2.z + v3.z;
        acc.w += v0.w + v1.w + v2.w + v3.w;
    }
    for (; i < e; i++) {
        int sv = csr[i];
        float4 v = h4[(size_t)sv * rs4 + lane];
        acc.x += v.x; acc.y += v.y; acc.z += v.z; acc.w += v.w;
    }
    float inv = (e > s) ? (1.f / (float)(e - s)) : 0.f;
    acc.x *= inv; acc.y *= inv; acc.z *= inv; acc.w *= inv;
    store_hilo(xh, xl, (size_t)(node >> 6) * 16384, (uint32_t)(node & 63),
               (uint32_t)(lane * 4), acc);
}

// ---------------------------------------------------------------------------
// mma.sync GEMM + ReLU over pre-swizzled bf16 tiles.
// 64-row tiles; smem 96KB (XH 16K | XL 16K | BH 32K | BL 32K); 2 CTAs/SM.
// 8 warps: warp w -> rows (w&1)*32..+32, cols (w>>1)*32..+32.
// Passes: XH*BH + XH*BL + XL*BH (fp32 accum).
// ---------------------------------------------------------------------------
#define GT 256
#define S_XH 0
#define S_XL 16384
#define S_BH 32768
#define S_BL 65536
#define GEMM_SMEM 98304

__global__ void __launch_bounds__(GT, 2)
gemm_mma_kernel(const unsigned char* __restrict__ xh,
                const unsigned char* __restrict__ xl,
                const unsigned char* __restrict__ wh,
                const unsigned char* __restrict__ wl,
                float* __restrict__ outBlk, int N, int outStride) {
    extern __shared__ char smem[];
    uint32_t sb = s2u(smem);
    int tid = threadIdx.x;
    int lane = tid & 31;
    int w = tid >> 5;
    int row0 = blockIdx.x * 64;

    // linear-copy prologue (layouts identical global<->smem)
    {
        const uint4* gx = reinterpret_cast<const uint4*>(xh + (size_t)blockIdx.x * 16384);
        const uint4* gl = reinterpret_cast<const uint4*>(xl + (size_t)blockIdx.x * 16384);
        uint4* sx = reinterpret_cast<uint4*>(smem + S_XH);
        uint4* sl = reinterpret_cast<uint4*>(smem + S_XL);
        #pragma unroll
        for (int i = 0; i < 4; i++) {
            sx[tid + i * GT] = gx[tid + i * GT];
            sl[tid + i * GT] = gl[tid + i * GT];
        }
        const uint4* gbh = reinterpret_cast<const uint4*>(wh);
        const uint4* gbl = reinterpret_cast<const uint4*>(wl);
        uint4* sbh = reinterpret_cast<uint4*>(smem + S_BH);
        uint4* sbl = reinterpret_cast<uint4*>(smem + S_BL);
        #pragma unroll
        for (int i = 0; i < 8; i++) {
            sbh[tid + i * GT] = gbh[tid + i * GT];
            sbl[tid + i * GT] = gbl[tid + i * GT];
        }
    }
    __syncthreads();

    const int rw = (w & 1) * 32;
    const int cw = (w >> 1) * 32;

    float acc[2][4][4];
    #pragma unroll
    for (int i = 0; i < 2; i++)
        #pragma unroll
        for (int j = 0; j < 4; j++)
            #pragma unroll
            for (int q = 0; q < 4; q++) acc[i][j][q] = 0.f;

    const int l2 = lane & 15;
    #pragma unroll
    for (int pass = 0; pass < 3; pass++) {
        const uint32_t aBase = sb + (pass == 2 ? S_XL : S_XH);
        const uint32_t bBase = sb + (pass == 1 ? S_BL : S_BH);
        #pragma unroll
        for (int kc = 0; kc < 8; kc++) {
            uint32_t a[2][4];
            #pragma unroll
            for (int i = 0; i < 2; i++) {
                uint32_t ar = (uint32_t)(rw + i * 16 + (lane & 15));
                uint32_t ak = (uint32_t)(kc * 16 + (lane >> 4) * 8);
                ldsm_x4(a[i], aBase + swz(ar, ak));
            }
            #pragma unroll
            for (int j = 0; j < 4; j++) {
                uint32_t b[2];
                uint32_t bk = (uint32_t)(kc * 16 + (l2 & 7) + ((l2 >> 3) & 1) * 8);
                uint32_t bn = (uint32_t)(cw + j * 8);
                ldsm_x2t(b, bBase + swz(bk, bn));
                mma_bf16(acc[0][j], a[0], b);
                mma_bf16(acc[1][j], a[1], b);
            }
        }
    }

    // epilogue: relu + direct fp32 stores into out block
    #pragma unroll
    for (int i = 0; i < 2; i++) {
        int rA = row0 + rw + i * 16 + (lane >> 2);
        int rB = rA + 8;
        #pragma unroll
        for (int j = 0; j < 4; j++) {
            int c = cw + j * 8 + (lane & 3) * 2;
            if (rA < N) {
                float2 v = make_float2(fmaxf(acc[i][j][0], 0.f),
                                       fmaxf(acc[i][j][1], 0.f));
                *reinterpret_cast<float2*>(outBlk + (size_t)rA * outStride + c) = v;
            }
            if (rB < N) {
                float2 v = make_float2(fmaxf(acc[i][j][2], 0.f),
                                       fmaxf(acc[i][j][3], 0.f));
                *reinterpret_cast<float2*>(outBlk + (size_t)rB * outStride + c) = v;
            }
        }
    }
}

// ---------------------------------------------------------------------------
// launch
// ---------------------------------------------------------------------------
extern "C" void kernel_launch(void* const* d_in, const int* in_sizes, int n_in,
                              void* d_out, int out_size) {
    const float* feat = (const float*)d_in[0];
    const int*   src  = (const int*)d_in[1];
    const int*   dst  = (const int*)d_in[2];
    const float* W0   = (const float*)d_in[3];
    const float* Ws   = (const float*)d_in[4];
    float* out = (float*)d_out;

    int N = in_sizes[0] / HID;
    int E = in_sizes[1];
    int L = in_sizes[4] / (HID * HID);
    int outStride = (L + 1) * HID;

    int* counts;    cudaGetSymbolAddress((void**)&counts, g_counts);
    int* rowstart;  cudaGetSymbolAddress((void**)&rowstart, g_rowstart);
    int* csr;       cudaGetSymbolAddress((void**)&csr, g_csr_src);
    unsigned char *xh, *xl, *wh, *wl;
    cudaGetSymbolAddress((void**)&xh, g_xh);
    cudaGetSymbolAddress((void**)&xl, g_xl);
    cudaGetSymbolAddress((void**)&wh, g_wh);
    cudaGetSymbolAddress((void**)&wl, g_wl);

    cudaFuncSetAttribute(gemm_mma_kernel, cudaFuncAttributeMaxDynamicSharedMemorySize,
                         GEMM_SMEM);

    // CSR build
    zero_counts_kernel<<<(N + 255) / 256, 256>>>(counts, N);
    count_kernel<<<(E + 255) / 256, 256>>>(dst, counts, E);
    scan_kernel<<<1, 1024>>>(counts, rowstart, N);
    scatter_kernel<<<(E + 255) / 256, 256>>>(src, dst, counts, csr, E);

    // weight + feat conversion
    w_conv_kernel<<<((L + 1) * 128 * 32 + 255) / 256, 256>>>(W0, Ws, wh, wl, L);
    feat_conv_kernel<<<(N * 32 + 255) / 256, 256>>>(feat, xh, xl, N);

    int gemm_grid = (N + 63) / 64;
    // layer 0: h0 = relu(feat @ W0) -> out[:, 0:128]
    gemm_mma_kernel<<<gemm_grid, GT, GEMM_SMEM>>>(xh, xl, wh, wl, out, N, outStride);

    int agg_grid = (N + 7) / 8;
    for (int l = 0; l < L; l++) {
        agg_kernel<<<agg_grid, 256>>>(
            reinterpret_cast<const float4*>(out + (size_t)l * HID), outStride / 4,
            rowstart, csr, xh, xl, N);
        gemm_mma_kernel<<<gemm_grid, GT, GEMM_SMEM>>>(
            xh, xl, wh + (size_t)(l + 1) * 32768, wl + (size_t)(l + 1) * 32768,
            out + (size_t)(l + 1) * HID, N, outStride);
    }
    (void)n_in; (void)out_size;
}